// round 9
// baseline (speedup 1.0000x reference)
#include <cuda_runtime.h>
#include <float.h>

#define BATCH 64
#define TOK   2048
#define DIM   768
#define POOL  1024
#define TOPK  8
#define SPLITS 32
#define TOKS  64               // tokens per stream CTA
#define D4    192              // float4 per row
#define NKP   16               // proj split-K (KC=48): 16*12 = 192 jobs
#define NKS   12               // sim  split-K (KC=64): 12*16 = 192 jobs
#define G     192              // persistent tail grid (max jobs per phase)
#define NORMC 171              // prompt-norm CTAs in stream kernel

// ---- scratch (static device arrays; no cudaMalloc anywhere) ----
__device__ unsigned g_xmax_enc[BATCH * DIM];   // zero-init < all encoded floats
__device__ float g_invp[POOL];
__device__ float g_xproj[BATCH * DIM];
__device__ float g_ssqp[BATCH * 3];
__device__ float g_ppart[BATCH * NKP * DIM];   // [b][sp][col]
__device__ float g_spart[BATCH * NKS * POOL];  // [b][sp][p]
__device__ float g_sim[BATCH * POOL];
__device__ int   g_rowidx[BATCH * TOPK];
__device__ int   g_major[TOPK];
__device__ unsigned g_count = 0;   // barrier state: self-resetting across replays
__device__ unsigned g_gen   = 0;

__device__ __forceinline__ float4 fmax4(float4 a, float4 b) {
    return make_float4(fmaxf(a.x, b.x), fmaxf(a.y, b.y),
                       fmaxf(a.z, b.z), fmaxf(a.w, b.w));
}
// order-preserving float <-> uint32 (monotone): max over keys == max over floats
__device__ __forceinline__ unsigned fenc(float f) {
    unsigned u = __float_as_uint(f);
    return (u & 0x80000000u) ? ~u : (u | 0x80000000u);
}
__device__ __forceinline__ float fdec(unsigned k) {
    unsigned u = (k & 0x80000000u) ? (k ^ 0x80000000u) : ~k;
    return __uint_as_float(u);
}

// ==================== kernel A: stream max + prompt norms ====================
__global__ void __launch_bounds__(192)
k_stream(const float* __restrict__ x, const float* __restrict__ prompt) {
    int bid = blockIdx.x, tid = threadIdx.x;
    if (bid < SPLITS * BATCH) {
        int s = bid & (SPLITS - 1), b = bid >> 5;
        const float4* xp = (const float4*)x + ((size_t)b * TOK + (size_t)s * TOKS) * D4 + tid;
        float4 m0 = __ldcs(xp + 0 * D4), m1 = __ldcs(xp + 1 * D4);
        float4 m2 = __ldcs(xp + 2 * D4), m3 = __ldcs(xp + 3 * D4);
        float4 m4 = __ldcs(xp + 4 * D4), m5 = __ldcs(xp + 5 * D4);
        float4 m6 = __ldcs(xp + 6 * D4), m7 = __ldcs(xp + 7 * D4);
#pragma unroll 7
        for (int t = 8; t < TOKS; t += 8) {
            const float4* p = xp + (size_t)t * D4;
            m0 = fmax4(m0, __ldcs(p + 0 * D4));
            m1 = fmax4(m1, __ldcs(p + 1 * D4));
            m2 = fmax4(m2, __ldcs(p + 2 * D4));
            m3 = fmax4(m3, __ldcs(p + 3 * D4));
            m4 = fmax4(m4, __ldcs(p + 4 * D4));
            m5 = fmax4(m5, __ldcs(p + 5 * D4));
            m6 = fmax4(m6, __ldcs(p + 6 * D4));
            m7 = fmax4(m7, __ldcs(p + 7 * D4));
        }
        float4 r = fmax4(fmax4(fmax4(m0, m1), fmax4(m2, m3)),
                         fmax4(fmax4(m4, m5), fmax4(m6, m7)));
        unsigned* dst = g_xmax_enc + (size_t)b * DIM + tid * 4;
        atomicMax(dst + 0, fenc(r.x));
        atomicMax(dst + 1, fenc(r.y));
        atomicMax(dst + 2, fenc(r.z));
        atomicMax(dst + 3, fenc(r.w));
    } else {
        int lane = tid & 31, w = tid >> 5;
        int p = (bid - SPLITS * BATCH) * 6 + w;
        if (p < POOL) {
            const float4* row = (const float4*)(prompt + (size_t)p * DIM);
            float s = 0.f;
#pragma unroll
            for (int j = lane; j < D4; j += 32) {
                float4 v = row[j];
                s += v.x * v.x + v.y * v.y + v.z * v.z + v.w * v.w;
            }
#pragma unroll
            for (int o = 16; o > 0; o >>= 1) s += __shfl_xor_sync(0xffffffffu, s, o);
            if (lane == 0) g_invp[p] = rsqrtf(fmaxf(s, 1e-12f));
        }
    }
}

// ==================== kernel B: persistent tail ==============================
__device__ __forceinline__ void grid_sync() {
    __syncthreads();
    if (threadIdx.x == 0) {
        __threadfence();
        volatile unsigned* genp = &g_gen;
        unsigned gen = *genp;
        if (atomicAdd(&g_count, 1u) == G - 1) {
            *(volatile unsigned*)&g_count = 0;
            __threadfence();
            *genp = gen + 1;
        } else {
            while (*genp == gen) __nanosleep(32);
        }
        __threadfence();
    }
    __syncthreads();
}

// 64x64-tile split-K GEMM chunk, software-pipelined inner loop.
// K4 = float4 K-steps (KC = 4*K4). DEC: A holds encoded-max keys.
template <int K4, bool DEC>
__device__ __forceinline__ void gemm64(const void* __restrict__ Araw,
                                       const float* __restrict__ B,
                                       float* __restrict__ dst, int cstride,
                                       int kc0, int c0, float* pool) {
    constexpr int SW = 4 * K4 + 4;           // padded row stride (floats)
    float (*xs)[SW] = (float(*)[SW])pool;
    float (*ws)[SW] = (float(*)[SW])(pool + 64 * SW);
    int tid = threadIdx.x;
#pragma unroll
    for (int it = 0; it < K4 / 4; it++) {
        int idx = tid + it * 256;            // 0 .. 64*K4-1
        int r = idx / K4, c4 = idx % K4;
        if (DEC) {
            uint4 e = *(const uint4*)((const unsigned*)Araw + (size_t)r * DIM + kc0 + c4 * 4);
            *(float4*)&xs[r][c4 * 4] = make_float4(fdec(e.x), fdec(e.y), fdec(e.z), fdec(e.w));
        } else {
            *(float4*)&xs[r][c4 * 4] = *(const float4*)((const float*)Araw + (size_t)r * DIM + kc0 + c4 * 4);
        }
        *(float4*)&ws[r][c4 * 4] = *(const float4*)(B + (size_t)(c0 + r) * DIM + kc0 + c4 * 4);
    }
    __syncthreads();
    int tx = tid & 15, ty = tid >> 4;        // 16x16 threads, 4x4 micro-tile
    float acc[4][4];
#pragma unroll
    for (int i = 0; i < 4; i++)
#pragma unroll
        for (int j = 0; j < 4; j++) acc[i][j] = 0.f;
    float4 a[4], b[4], an[4], bn[4];
#pragma unroll
    for (int i = 0; i < 4; i++) {
        a[i] = *(float4*)&xs[ty * 4 + i][0];
        b[i] = *(float4*)&ws[tx * 4 + i][0];
    }
#pragma unroll
    for (int k4 = 0; k4 < K4; k4++) {
        if (k4 + 1 < K4) {                   // prefetch next k-step (hides LDS lat)
#pragma unroll
            for (int i = 0; i < 4; i++) {
                an[i] = *(float4*)&xs[ty * 4 + i][(k4 + 1) * 4];
                bn[i] = *(float4*)&ws[tx * 4 + i][(k4 + 1) * 4];
            }
        }
#pragma unroll
        for (int i = 0; i < 4; i++)
#pragma unroll
            for (int j = 0; j < 4; j++) {
                acc[i][j] += a[i].x * b[j].x;
                acc[i][j] += a[i].y * b[j].y;
                acc[i][j] += a[i].z * b[j].z;
                acc[i][j] += a[i].w * b[j].w;
            }
#pragma unroll
        for (int i = 0; i < 4; i++) { a[i] = an[i]; b[i] = bn[i]; }
    }
    __syncthreads();
#pragma unroll
    for (int i = 0; i < 4; i++) {
        float4 v = make_float4(acc[i][0], acc[i][1], acc[i][2], acc[i][3]);
        *(float4*)(dst + (size_t)(ty * 4 + i) * cstride + c0 + tx * 4) = v;
    }
}

// warp-register iterative top-8 with JAX tie rule (lowest index wins).
__device__ __forceinline__ void warp_top8_f(float* v, int lane, int* picks) {
    for (int k = 0; k < TOPK; k++) {
        float bv = -FLT_MAX; int bj = 0;
#pragma unroll
        for (int j = 0; j < 32; j++)
            if (v[j] > bv) { bv = v[j]; bj = j; }     // ascending j: lowest idx on tie
        float rv = bv; int rgi = lane + 32 * bj;
#pragma unroll
        for (int o = 16; o > 0; o >>= 1) {
            float ov = __shfl_xor_sync(0xffffffffu, rv, o);
            int   oi = __shfl_xor_sync(0xffffffffu, rgi, o);
            if (ov > rv || (ov == rv && oi < rgi)) { rv = ov; rgi = oi; }
        }
        picks[k] = rgi;
        if (lane == (rgi & 31)) {
            int slot = rgi >> 5;
#pragma unroll
            for (int j = 0; j < 32; j++)
                if (j == slot) v[j] = -FLT_MAX;
        }
    }
}

__global__ void __launch_bounds__(256, 2)
k_tail(const float* __restrict__ prompt, const float* __restrict__ W,
       float* __restrict__ out) {
    __shared__ float s_pool[2 * 64 * 68];   // 34.8 KB, phase-unioned
    int tid = threadIdx.x, bid = blockIdx.x;
    int lane = tid & 31;

    // -------- B1: proj split-K GEMM, decoding max-keys inline (192 jobs) ----
    if (bid < NKP * (DIM / 64)) {            // 16 * 12 = 192
        int ct = bid % (DIM / 64), kt = bid / (DIM / 64);
        // partials layout [b][kt][col]: dst row stride = NKP*DIM
        gemm64<12, true>(g_xmax_enc, W, g_ppart + (size_t)kt * DIM, NKP * DIM,
                         kt * 48, ct * 64, s_pool);
    }
    grid_sync();

    // -------- B2: reduce proj partials + chunk ssq + key reset (192 jobs) ---
    if (bid < BATCH * 3) {
        int b = bid / 3, chunk = bid % 3;
        int col = chunk * 256 + tid;
        const float* base = g_ppart + (size_t)b * NKP * DIM + col;   // contiguous blocks
        float s = 0.f;
#pragma unroll
        for (int sp = 0; sp < NKP; sp++)
            s += base[(size_t)sp * DIM];
        g_xproj[b * DIM + col] = s;
        g_xmax_enc[b * DIM + col] = 0u;      // reset for next graph replay
        float* red = s_pool;
        red[tid] = s * s; __syncthreads();
        for (int st = 128; st > 0; st >>= 1) {
            if (tid < st) red[tid] += red[tid + st];
            __syncthreads();
        }
        if (tid == 0) g_ssqp[bid] = red[0];
    }
    grid_sync();

    // -------- B3: sim split-K GEMM on unnormalized xproj (192 jobs) ---------
    if (bid < NKS * (POOL / 64)) {           // 12 * 16 = 192
        int ct = bid % (POOL / 64), kt = bid / (POOL / 64);
        gemm64<16, false>(g_xproj, prompt, g_spart + (size_t)kt * POOL, NKS * POOL,
                          kt * 64, ct * 64, s_pool);
    }
    grid_sync();

    // -------- B4: reduce sim + scale + warp-register top-8 (64 CTAs) --------
    if (bid < BATCH) {
        int b = bid;
        float invx = rsqrtf(fmaxf(g_ssqp[b * 3 + 0] + g_ssqp[b * 3 + 1]
                                  + g_ssqp[b * 3 + 2], 1e-12f));
        float* sv = s_pool;                  // [1024]
        const float* base = g_spart + (size_t)b * NKS * POOL;
#pragma unroll
        for (int j = 0; j < 4; j++) {
            int p = tid + 256 * j;
            float s = 0.f;
#pragma unroll
            for (int sp = 0; sp < NKS; sp++)
                s += base[(size_t)sp * POOL + p];    // contiguous 4KB blocks
            s *= g_invp[p] * invx;
            sv[p] = s;
            g_sim[b * POOL + p] = s;
        }
        __syncthreads();
        if (tid < 32) {
            float v[32];
#pragma unroll
            for (int j = 0; j < 32; j++) v[j] = sv[lane + 32 * j];
            int picks[TOPK];
            warp_top8_f(v, lane, picks);
            if (lane < TOPK) g_rowidx[b * TOPK + lane] = picks[lane];
        }
    }
    grid_sync();

    // -------- B5: vote (bincount + warp top-8 on counts) + reduce_sim -------
    if (bid == 0) {
        int*   cnt     = (int*)s_pool;       // [1024]
        float* rf      = s_pool + 1024;      // [256]
        int*   major_s = (int*)(s_pool + 1280);  // [8]
        for (int j = tid; j < POOL; j += 256) cnt[j] = 0;
        __syncthreads();
        for (int j = tid; j < BATCH * TOPK; j += 256) atomicAdd(&cnt[g_rowidx[j]], 1);
        __syncthreads();
        if (tid < 32) {
            float v[32];
#pragma unroll
            for (int j = 0; j < 32; j++) v[j] = (float)cnt[lane + 32 * j];  // counts <= 512: exact in fp32
            int picks[TOPK];
            warp_top8_f(v, lane, picks);
            if (lane < TOPK) { major_s[lane] = picks[lane]; g_major[lane] = picks[lane]; }
        }
        __syncthreads();
        float s = 0.f;
        for (int j = tid; j < BATCH * TOPK; j += 256) {
            int b = j >> 3, k = j & 7;
            s += g_sim[b * POOL + major_s[k]];
        }
        rf[tid] = s; __syncthreads();
        for (int st = 128; st > 0; st >>= 1) {
            if (tid < st) rf[tid] += rf[tid + st];
            __syncthreads();
        }
        if (tid == 0) out[0] = rf[0] / (float)BATCH;
    }
    grid_sync();

    // -------- B6: gather batched_prompt (scalar stores: out+1 alignment) ----
    for (int row = bid; row < BATCH * TOPK; row += G) {
        int k = row & 7;
        int pid = g_major[k];
        const float* src = prompt + (size_t)pid * DIM;
        float* dst = out + 1 + (size_t)row * DIM;
        if (tid < 192) {
            float4 v = ((const float4*)src)[tid];
            dst[tid * 4 + 0] = v.x;
            dst[tid * 4 + 1] = v.y;
            dst[tid * 4 + 2] = v.z;
            dst[tid * 4 + 3] = v.w;
        }
    }
}

extern "C" void kernel_launch(void* const* d_in, const int* in_sizes, int n_in,
                              void* d_out, int out_size) {
    const float* x      = (const float*)d_in[0];   // [64, 2048, 768]
    const float* prompt = (const float*)d_in[1];   // [1024, 768]
    const float* W      = (const float*)d_in[2];   // [768, 768]
    float* out = (float*)d_out;                    // [1 + 64*8*768]
    k_stream<<<SPLITS * BATCH + NORMC, 192>>>(x, prompt);
    k_tail  <<<G, 256>>>(prompt, W, out);
}

// round 10
// speedup vs baseline: 1.0177x; 1.0177x over previous
#include <cuda_runtime.h>
#include <float.h>

#define BATCH 64
#define TOK   2048
#define DIM   768
#define POOL  1024
#define TOPK  8
#define SPLITS 32
#define TOKS  64               // tokens per stream CTA
#define D4    192              // float4 per row
#define NKP   24               // proj split-K (KC=32): 24*12 = 288 jobs
#define NKS   16               // sim  split-K (KC=48): 16*16 = 256 jobs
#define G     296              // persistent tail grid: 2 CTAs/SM
#define NORMC 171              // prompt-norm CTAs in stream kernel

// ---- scratch (static device arrays; no cudaMalloc anywhere) ----
__device__ unsigned g_xmax_enc[BATCH * DIM];   // zero-init < all encoded floats
__device__ float g_invp[POOL];
__device__ float g_xproj[BATCH * DIM];
__device__ float g_ssqp[BATCH * 3];
__device__ float g_ppart[BATCH * NKP * DIM];   // [b][sp][col]  (contiguous reduce)
__device__ float g_spart[BATCH * NKS * POOL];  // [b][sp][p]
__device__ float g_sim[BATCH * POOL];
__device__ int   g_rowidx[BATCH * TOPK];
__device__ int   g_major[TOPK];
__device__ unsigned g_count = 0;   // barrier state: self-resetting across replays
__device__ unsigned g_gen   = 0;

__device__ __forceinline__ float4 fmax4(float4 a, float4 b) {
    return make_float4(fmaxf(a.x, b.x), fmaxf(a.y, b.y),
                       fmaxf(a.z, b.z), fmaxf(a.w, b.w));
}
// order-preserving float <-> uint32 (monotone): max over keys == max over floats
__device__ __forceinline__ unsigned fenc(float f) {
    unsigned u = __float_as_uint(f);
    return (u & 0x80000000u) ? ~u : (u | 0x80000000u);
}
__device__ __forceinline__ float fdec(unsigned k) {
    unsigned u = (k & 0x80000000u) ? (k ^ 0x80000000u) : ~k;
    return __uint_as_float(u);
}

// ==================== kernel A: stream max + prompt norms ====================
__global__ void __launch_bounds__(192)
k_stream(const float* __restrict__ x, const float* __restrict__ prompt) {
    int bid = blockIdx.x, tid = threadIdx.x;
    if (bid < SPLITS * BATCH) {
        int s = bid & (SPLITS - 1), b = bid >> 5;
        const float4* xp = (const float4*)x + ((size_t)b * TOK + (size_t)s * TOKS) * D4 + tid;
        float4 m0 = __ldcs(xp + 0 * D4), m1 = __ldcs(xp + 1 * D4);
        float4 m2 = __ldcs(xp + 2 * D4), m3 = __ldcs(xp + 3 * D4);
        float4 m4 = __ldcs(xp + 4 * D4), m5 = __ldcs(xp + 5 * D4);
        float4 m6 = __ldcs(xp + 6 * D4), m7 = __ldcs(xp + 7 * D4);
#pragma unroll 7
        for (int t = 8; t < TOKS; t += 8) {
            const float4* p = xp + (size_t)t * D4;
            m0 = fmax4(m0, __ldcs(p + 0 * D4));
            m1 = fmax4(m1, __ldcs(p + 1 * D4));
            m2 = fmax4(m2, __ldcs(p + 2 * D4));
            m3 = fmax4(m3, __ldcs(p + 3 * D4));
            m4 = fmax4(m4, __ldcs(p + 4 * D4));
            m5 = fmax4(m5, __ldcs(p + 5 * D4));
            m6 = fmax4(m6, __ldcs(p + 6 * D4));
            m7 = fmax4(m7, __ldcs(p + 7 * D4));
        }
        float4 r = fmax4(fmax4(fmax4(m0, m1), fmax4(m2, m3)),
                         fmax4(fmax4(m4, m5), fmax4(m6, m7)));
        unsigned* dst = g_xmax_enc + (size_t)b * DIM + tid * 4;
        atomicMax(dst + 0, fenc(r.x));
        atomicMax(dst + 1, fenc(r.y));
        atomicMax(dst + 2, fenc(r.z));
        atomicMax(dst + 3, fenc(r.w));
    } else {
        int lane = tid & 31, w = tid >> 5;
        int p = (bid - SPLITS * BATCH) * 6 + w;
        if (p < POOL) {
            const float4* row = (const float4*)(prompt + (size_t)p * DIM);
            float s = 0.f;
#pragma unroll
            for (int j = lane; j < D4; j += 32) {
                float4 v = row[j];
                s += v.x * v.x + v.y * v.y + v.z * v.z + v.w * v.w;
            }
#pragma unroll
            for (int o = 16; o > 0; o >>= 1) s += __shfl_xor_sync(0xffffffffu, s, o);
            if (lane == 0) g_invp[p] = rsqrtf(fmaxf(s, 1e-12f));
        }
    }
}

// ==================== kernel B: persistent tail ==============================
__device__ __forceinline__ void grid_sync() {
    __syncthreads();
    if (threadIdx.x == 0) {
        __threadfence();
        volatile unsigned* genp = &g_gen;
        unsigned gen = *genp;
        if (atomicAdd(&g_count, 1u) == G - 1) {
            *(volatile unsigned*)&g_count = 0;
            __threadfence();
            *genp = gen + 1;
        } else {
            while (*genp == gen) __nanosleep(32);
        }
        __threadfence();
    }
    __syncthreads();
}

// 64x64-tile split-K GEMM chunk, software-pipelined inner loop.
// K4 = float4 K-steps (KC = 4*K4). DEC: A holds encoded-max keys.
template <int K4, bool DEC>
__device__ __forceinline__ void gemm64(const void* __restrict__ Araw,
                                       const float* __restrict__ B,
                                       float* __restrict__ dst, int cstride,
                                       int kc0, int c0, float* pool) {
    constexpr int SW = 4 * K4 + 4;           // padded row stride (floats)
    float (*xs)[SW] = (float(*)[SW])pool;
    float (*ws)[SW] = (float(*)[SW])(pool + 64 * SW);
    int tid = threadIdx.x;
#pragma unroll
    for (int it = 0; it < K4 / 4; it++) {
        int idx = tid + it * 256;            // 0 .. 64*K4-1
        int r = idx / K4, c4 = idx % K4;
        if (DEC) {
            uint4 e = *(const uint4*)((const unsigned*)Araw + (size_t)r * DIM + kc0 + c4 * 4);
            *(float4*)&xs[r][c4 * 4] = make_float4(fdec(e.x), fdec(e.y), fdec(e.z), fdec(e.w));
        } else {
            *(float4*)&xs[r][c4 * 4] = *(const float4*)((const float*)Araw + (size_t)r * DIM + kc0 + c4 * 4);
        }
        *(float4*)&ws[r][c4 * 4] = *(const float4*)(B + (size_t)(c0 + r) * DIM + kc0 + c4 * 4);
    }
    __syncthreads();
    int tx = tid & 15, ty = tid >> 4;        // 16x16 threads, 4x4 micro-tile
    float acc[4][4];
#pragma unroll
    for (int i = 0; i < 4; i++)
#pragma unroll
        for (int j = 0; j < 4; j++) acc[i][j] = 0.f;
    float4 a[4], b[4], an[4], bn[4];
#pragma unroll
    for (int i = 0; i < 4; i++) {
        a[i] = *(float4*)&xs[ty * 4 + i][0];
        b[i] = *(float4*)&ws[tx * 4 + i][0];
    }
#pragma unroll
    for (int k4 = 0; k4 < K4; k4++) {
        if (k4 + 1 < K4) {                   // prefetch next k-step (hides LDS lat)
#pragma unroll
            for (int i = 0; i < 4; i++) {
                an[i] = *(float4*)&xs[ty * 4 + i][(k4 + 1) * 4];
                bn[i] = *(float4*)&ws[tx * 4 + i][(k4 + 1) * 4];
            }
        }
#pragma unroll
        for (int i = 0; i < 4; i++)
#pragma unroll
            for (int j = 0; j < 4; j++) {
                acc[i][j] += a[i].x * b[j].x;
                acc[i][j] += a[i].y * b[j].y;
                acc[i][j] += a[i].z * b[j].z;
                acc[i][j] += a[i].w * b[j].w;
            }
#pragma unroll
        for (int i = 0; i < 4; i++) { a[i] = an[i]; b[i] = bn[i]; }
    }
    __syncthreads();
#pragma unroll
    for (int i = 0; i < 4; i++) {
        float4 v = make_float4(acc[i][0], acc[i][1], acc[i][2], acc[i][3]);
        *(float4*)(dst + (size_t)(ty * 4 + i) * cstride + c0 + tx * 4) = v;
    }
}

// warp-register iterative top-8 with JAX tie rule (lowest index wins).
__device__ __forceinline__ void warp_top8_f(float* v, int lane, int* picks) {
    for (int k = 0; k < TOPK; k++) {
        float bv = -FLT_MAX; int bj = 0;
#pragma unroll
        for (int j = 0; j < 32; j++)
            if (v[j] > bv) { bv = v[j]; bj = j; }     // ascending j: lowest idx on tie
        float rv = bv; int rgi = lane + 32 * bj;
#pragma unroll
        for (int o = 16; o > 0; o >>= 1) {
            float ov = __shfl_xor_sync(0xffffffffu, rv, o);
            int   oi = __shfl_xor_sync(0xffffffffu, rgi, o);
            if (ov > rv || (ov == rv && oi < rgi)) { rv = ov; rgi = oi; }
        }
        picks[k] = rgi;
        if (lane == (rgi & 31)) {
            int slot = rgi >> 5;
#pragma unroll
            for (int j = 0; j < 32; j++)
                if (j == slot) v[j] = -FLT_MAX;
        }
    }
}

__global__ void __launch_bounds__(256, 2)
k_tail(const float* __restrict__ prompt, const float* __restrict__ W,
       float* __restrict__ out) {
    __shared__ float s_pool[2 * 64 * 52];   // 26.6 KB, phase-unioned
    int tid = threadIdx.x, bid = blockIdx.x;
    int lane = tid & 31;

    // -------- B1: proj split-K GEMM, decoding max-keys inline (288 jobs) ----
    if (bid < NKP * (DIM / 64)) {            // 24 * 12 = 288
        int ct = bid % (DIM / 64), kt = bid / (DIM / 64);
        // partials layout [b][kt][col]: dst row stride = NKP*DIM
        gemm64<8, true>(g_xmax_enc, W, g_ppart + (size_t)kt * DIM, NKP * DIM,
                        kt * 32, ct * 64, s_pool);
    }
    grid_sync();

    // -------- B2: reduce proj partials + chunk ssq + key reset (192 jobs) ---
    if (bid < BATCH * 3) {
        int b = bid / 3, chunk = bid % 3;
        int col = chunk * 256 + tid;
        const float* base = g_ppart + (size_t)b * NKP * DIM + col;   // contiguous blocks
        float s = 0.f;
#pragma unroll
        for (int sp = 0; sp < NKP; sp++)
            s += base[(size_t)sp * DIM];
        g_xproj[b * DIM + col] = s;
        g_xmax_enc[b * DIM + col] = 0u;      // reset for next graph replay
        float* red = s_pool;
        red[tid] = s * s; __syncthreads();
        for (int st = 128; st > 0; st >>= 1) {
            if (tid < st) red[tid] += red[tid + st];
            __syncthreads();
        }
        if (tid == 0) g_ssqp[bid] = red[0];
    }
    grid_sync();

    // -------- B3: sim split-K GEMM on unnormalized xproj (256 jobs) ---------
    if (bid < NKS * (POOL / 64)) {           // 16 * 16 = 256
        int ct = bid % (POOL / 64), kt = bid / (POOL / 64);
        gemm64<12, false>(g_xproj, prompt, g_spart + (size_t)kt * POOL, NKS * POOL,
                          kt * 48, ct * 64, s_pool);
    }
    grid_sync();

    // -------- B4: reduce sim + scale + warp-register top-8 (64 CTAs) --------
    if (bid < BATCH) {
        int b = bid;
        float invx = rsqrtf(fmaxf(g_ssqp[b * 3 + 0] + g_ssqp[b * 3 + 1]
                                  + g_ssqp[b * 3 + 2], 1e-12f));
        float* sv = s_pool;                  // [1024]
        const float* base = g_spart + (size_t)b * NKS * POOL;
#pragma unroll
        for (int j = 0; j < 4; j++) {
            int p = tid + 256 * j;
            float s = 0.f;
#pragma unroll
            for (int sp = 0; sp < NKS; sp++)
                s += base[(size_t)sp * POOL + p];    // contiguous 4KB blocks
            s *= g_invp[p] * invx;
            sv[p] = s;
            g_sim[b * POOL + p] = s;
        }
        __syncthreads();
        if (tid < 32) {
            float v[32];
#pragma unroll
            for (int j = 0; j < 32; j++) v[j] = sv[lane + 32 * j];
            int picks[TOPK];
            warp_top8_f(v, lane, picks);
            if (lane < TOPK) g_rowidx[b * TOPK + lane] = picks[lane];
        }
    }
    grid_sync();

    // -------- B5: vote (bincount + warp top-8 on counts) + reduce_sim -------
    if (bid == 0) {
        int*   cnt     = (int*)s_pool;       // [1024]
        float* rf      = s_pool + 1024;      // [256]
        int*   major_s = (int*)(s_pool + 1280);  // [8]
        for (int j = tid; j < POOL; j += 256) cnt[j] = 0;
        __syncthreads();
        for (int j = tid; j < BATCH * TOPK; j += 256) atomicAdd(&cnt[g_rowidx[j]], 1);
        __syncthreads();
        if (tid < 32) {
            float v[32];
#pragma unroll
            for (int j = 0; j < 32; j++) v[j] = (float)cnt[lane + 32 * j];  // counts <= 512: exact in fp32
            int picks[TOPK];
            warp_top8_f(v, lane, picks);
            if (lane < TOPK) { major_s[lane] = picks[lane]; g_major[lane] = picks[lane]; }
        }
        __syncthreads();
        float s = 0.f;
        for (int j = tid; j < BATCH * TOPK; j += 256) {
            int b = j >> 3, k = j & 7;
            s += g_sim[b * POOL + major_s[k]];
        }
        rf[tid] = s; __syncthreads();
        for (int st = 128; st > 0; st >>= 1) {
            if (tid < st) rf[tid] += rf[tid + st];
            __syncthreads();
        }
        if (tid == 0) out[0] = rf[0] / (float)BATCH;
    }
    grid_sync();

    // -------- B6: gather batched_prompt (scalar stores: out+1 alignment) ----
    for (int row = bid; row < BATCH * TOPK; row += G) {
        int k = row & 7;
        int pid = g_major[k];
        const float* src = prompt + (size_t)pid * DIM;
        float* dst = out + 1 + (size_t)row * DIM;
        if (tid < 192) {
            float4 v = ((const float4*)src)[tid];
            dst[tid * 4 + 0] = v.x;
            dst[tid * 4 + 1] = v.y;
            dst[tid * 4 + 2] = v.z;
            dst[tid * 4 + 3] = v.w;
        }
    }
}

extern "C" void kernel_launch(void* const* d_in, const int* in_sizes, int n_in,
                              void* d_out, int out_size) {
    const float* x      = (const float*)d_in[0];   // [64, 2048, 768]
    const float* prompt = (const float*)d_in[1];   // [1024, 768]
    const float* W      = (const float*)d_in[2];   // [768, 768]
    float* out = (float*)d_out;                    // [1 + 64*8*768]
    k_stream<<<SPLITS * BATCH + NORMC, 192>>>(x, prompt);
    k_tail  <<<G, 256>>>(prompt, W, out);
}

// round 12
// speedup vs baseline: 1.1078x; 1.0885x over previous
#include <cuda_runtime.h>
#include <float.h>

#define BATCH 64
#define TOK   2048
#define DIM   768
#define POOL  1024
#define TOPK  8
#define SPLITS 32
#define TOKS  64               // tokens per stream CTA
#define D4    192              // float4 per row
#define NKP   24               // proj split-K (KC=32): 24*12 = 288 jobs
#define NKS   16               // sim  split-K (KC=48): 16*16 = 256 jobs
#define G     296              // persistent tail grid: 2 CTAs/SM
#define NORMC 171              // prompt-norm CTAs in stream kernel

// ---- scratch (static device arrays; no cudaMalloc anywhere) ----
__device__ unsigned g_xmax_enc[BATCH * DIM];   // zero-init < all encoded floats
__device__ float g_invp[POOL];
__device__ float g_xproj[BATCH * DIM];
__device__ float g_ssqp[BATCH * 3];
__device__ float g_ppart[NKP * BATCH * DIM];   // [sp][b][col]
__device__ float g_spart[NKS * BATCH * POOL];  // [sp][b][p]
__device__ float g_sim[BATCH * POOL];
__device__ int   g_rowidx[BATCH * TOPK];
__device__ int   g_major[TOPK];
__device__ unsigned g_count = 0;   // barrier state: self-resetting across replays
__device__ unsigned g_gen   = 0;

__device__ __forceinline__ float4 fmax4(float4 a, float4 b) {
    return make_float4(fmaxf(a.x, b.x), fmaxf(a.y, b.y),
                       fmaxf(a.z, b.z), fmaxf(a.w, b.w));
}
// order-preserving float <-> uint32 (monotone): max over keys == max over floats
__device__ __forceinline__ unsigned fenc(float f) {
    unsigned u = __float_as_uint(f);
    return (u & 0x80000000u) ? ~u : (u | 0x80000000u);
}
__device__ __forceinline__ float fdec(unsigned k) {
    unsigned u = (k & 0x80000000u) ? (k ^ 0x80000000u) : ~k;
    return __uint_as_float(u);
}

// ==================== kernel A: stream max + prompt norms ====================
__global__ void __launch_bounds__(192)
k_stream(const float* __restrict__ x, const float* __restrict__ prompt) {
    int bid = blockIdx.x, tid = threadIdx.x;
    if (bid < SPLITS * BATCH) {
        int s = bid & (SPLITS - 1), b = bid >> 5;
        const float4* xp = (const float4*)x + ((size_t)b * TOK + (size_t)s * TOKS) * D4 + tid;
        float4 m0 = __ldcs(xp + 0 * D4), m1 = __ldcs(xp + 1 * D4);
        float4 m2 = __ldcs(xp + 2 * D4), m3 = __ldcs(xp + 3 * D4);
        float4 m4 = __ldcs(xp + 4 * D4), m5 = __ldcs(xp + 5 * D4);
        float4 m6 = __ldcs(xp + 6 * D4), m7 = __ldcs(xp + 7 * D4);
#pragma unroll 7
        for (int t = 8; t < TOKS; t += 8) {
            const float4* p = xp + (size_t)t * D4;
            m0 = fmax4(m0, __ldcs(p + 0 * D4));
            m1 = fmax4(m1, __ldcs(p + 1 * D4));
            m2 = fmax4(m2, __ldcs(p + 2 * D4));
            m3 = fmax4(m3, __ldcs(p + 3 * D4));
            m4 = fmax4(m4, __ldcs(p + 4 * D4));
            m5 = fmax4(m5, __ldcs(p + 5 * D4));
            m6 = fmax4(m6, __ldcs(p + 6 * D4));
            m7 = fmax4(m7, __ldcs(p + 7 * D4));
        }
        float4 r = fmax4(fmax4(fmax4(m0, m1), fmax4(m2, m3)),
                         fmax4(fmax4(m4, m5), fmax4(m6, m7)));
        unsigned* dst = g_xmax_enc + (size_t)b * DIM + tid * 4;
        atomicMax(dst + 0, fenc(r.x));
        atomicMax(dst + 1, fenc(r.y));
        atomicMax(dst + 2, fenc(r.z));
        atomicMax(dst + 3, fenc(r.w));
    } else {
        int lane = tid & 31, w = tid >> 5;
        int p = (bid - SPLITS * BATCH) * 6 + w;
        if (p < POOL) {
            const float4* row = (const float4*)(prompt + (size_t)p * DIM);
            float s = 0.f;
#pragma unroll
            for (int j = lane; j < D4; j += 32) {
                float4 v = row[j];
                s += v.x * v.x + v.y * v.y + v.z * v.z + v.w * v.w;
            }
#pragma unroll
            for (int o = 16; o > 0; o >>= 1) s += __shfl_xor_sync(0xffffffffu, s, o);
            if (lane == 0) g_invp[p] = rsqrtf(fmaxf(s, 1e-12f));
        }
    }
}

// ==================== kernel B: persistent tail ==============================
__device__ __forceinline__ void grid_sync() {
    __syncthreads();
    if (threadIdx.x == 0) {
        __threadfence();
        volatile unsigned* genp = &g_gen;
        unsigned gen = *genp;
        if (atomicAdd(&g_count, 1u) == G - 1) {
            *(volatile unsigned*)&g_count = 0;
            __threadfence();
            *genp = gen + 1;
        } else {
            while (*genp == gen) __nanosleep(32);
        }
        __threadfence();
    }
    __syncthreads();
}

// 64x64-tile split-K GEMM chunk, software-pipelined inner loop.
// K4 = float4 K-steps (KC = 4*K4). DEC: A holds encoded-max keys.
// SW = 4*K4+4 keeps float4 alignment; SW16 = K4+1 is ODD, and the fragment
// mapping (rows ty+16i, cols tx+16j) gives lane address deltas of SW16
// 16B-units -> all 8 bank-groups covered -> conflict-free LDS.128.
template <int K4, bool DEC>
__device__ __forceinline__ void gemm64(const void* __restrict__ Araw,
                                       const float* __restrict__ B,
                                       float* __restrict__ dst, int cstride,
                                       int kc0, int c0, float* pool) {
    constexpr int SW = 4 * K4 + 4;           // SW % 4 == 0 (alignment), (SW/4) odd
    static_assert(((SW / 4) & 1) == 1, "SW16 must be odd for conflict-free LDS");
    float (*xs)[SW] = (float(*)[SW])pool;
    float (*ws)[SW] = (float(*)[SW])(pool + 64 * SW);
    int tid = threadIdx.x;
#pragma unroll
    for (int it = 0; it < K4 / 4; it++) {
        int idx = tid + it * 256;            // 0 .. 64*K4-1
        int r = idx / K4, c4 = idx % K4;
        if (DEC) {
            uint4 e = *(const uint4*)((const unsigned*)Araw + (size_t)r * DIM + kc0 + c4 * 4);
            *(float4*)&xs[r][c4 * 4] = make_float4(fdec(e.x), fdec(e.y), fdec(e.z), fdec(e.w));
        } else {
            *(float4*)&xs[r][c4 * 4] = *(const float4*)((const float*)Araw + (size_t)r * DIM + kc0 + c4 * 4);
        }
        *(float4*)&ws[r][c4 * 4] = *(const float4*)(B + (size_t)(c0 + r) * DIM + kc0 + c4 * 4);
    }
    __syncthreads();
    int tx = tid & 15, ty = tid >> 4;        // 16x16 threads; strided 4x4 micro-tile
    float acc[4][4];
#pragma unroll
    for (int i = 0; i < 4; i++)
#pragma unroll
        for (int j = 0; j < 4; j++) acc[i][j] = 0.f;
    float4 a[4], b[4], an[4], bn[4];
#pragma unroll
    for (int i = 0; i < 4; i++) {
        a[i] = *(float4*)&xs[ty + 16 * i][0];
        b[i] = *(float4*)&ws[tx + 16 * i][0];
    }
#pragma unroll
    for (int k4 = 0; k4 < K4; k4++) {
        if (k4 + 1 < K4) {                   // prefetch next k-step (hides LDS lat)
#pragma unroll
            for (int i = 0; i < 4; i++) {
                an[i] = *(float4*)&xs[ty + 16 * i][(k4 + 1) * 4];
                bn[i] = *(float4*)&ws[tx + 16 * i][(k4 + 1) * 4];
            }
        }
#pragma unroll
        for (int i = 0; i < 4; i++)
#pragma unroll
            for (int j = 0; j < 4; j++) {
                acc[i][j] += a[i].x * b[j].x;
                acc[i][j] += a[i].y * b[j].y;
                acc[i][j] += a[i].z * b[j].z;
                acc[i][j] += a[i].w * b[j].w;
            }
#pragma unroll
        for (int i = 0; i < 4; i++) { a[i] = an[i]; b[i] = bn[i]; }
    }
    __syncthreads();
    // scalar stores: row ty+16i, col c0 + tx + 16j (coalesced across tx)
#pragma unroll
    for (int i = 0; i < 4; i++)
#pragma unroll
        for (int j = 0; j < 4; j++)
            dst[(size_t)(ty + 16 * i) * cstride + c0 + tx + 16 * j] = acc[i][j];
}

// warp-register iterative top-8 with JAX tie rule (lowest index wins).
__device__ __forceinline__ void warp_top8_f(float* v, int lane, int* picks) {
    for (int k = 0; k < TOPK; k++) {
        float bv = -FLT_MAX; int bj = 0;
#pragma unroll
        for (int j = 0; j < 32; j++)
            if (v[j] > bv) { bv = v[j]; bj = j; }     // ascending j: lowest idx on tie
        float rv = bv; int rgi = lane + 32 * bj;
#pragma unroll
        for (int o = 16; o > 0; o >>= 1) {
            float ov = __shfl_xor_sync(0xffffffffu, rv, o);
            int   oi = __shfl_xor_sync(0xffffffffu, rgi, o);
            if (ov > rv || (ov == rv && oi < rgi)) { rv = ov; rgi = oi; }
        }
        picks[k] = rgi;
        if (lane == (rgi & 31)) {
            int slot = rgi >> 5;
#pragma unroll
            for (int j = 0; j < 32; j++)
                if (j == slot) v[j] = -FLT_MAX;
        }
    }
}

__global__ void __launch_bounds__(256, 2)
k_tail(const float* __restrict__ prompt, const float* __restrict__ W,
       float* __restrict__ out) {
    __shared__ float s_pool[2 * 64 * 52];   // 26.6 KB, phase-unioned (max SW=52)
    int tid = threadIdx.x, bid = blockIdx.x;
    int lane = tid & 31;

    // -------- B1: proj split-K GEMM, decoding max-keys inline (288 jobs) ----
    if (bid < NKP * (DIM / 64)) {            // 24 * 12 = 288
        int ct = bid % (DIM / 64), kt = bid / (DIM / 64);
        gemm64<8, true>(g_xmax_enc, W, g_ppart + (size_t)kt * BATCH * DIM, DIM,
                        kt * 32, ct * 64, s_pool);
    }
    grid_sync();

    // -------- B2: reduce proj partials + chunk ssq + key reset (192 jobs) ---
    if (bid < BATCH * 3) {
        int b = bid / 3, chunk = bid % 3;
        int col = chunk * 256 + tid;
        float s = 0.f;
#pragma unroll
        for (int sp = 0; sp < NKP; sp++)
            s += g_ppart[(size_t)sp * BATCH * DIM + (size_t)b * DIM + col];
        g_xproj[b * DIM + col] = s;
        g_xmax_enc[b * DIM + col] = 0u;      // reset for next graph replay
        float* red = s_pool;
        red[tid] = s * s; __syncthreads();
        for (int st = 128; st > 0; st >>= 1) {
            if (tid < st) red[tid] += red[tid + st];
            __syncthreads();
        }
        if (tid == 0) g_ssqp[bid] = red[0];
    }
    grid_sync();

    // -------- B3: sim split-K GEMM on unnormalized xproj (256 jobs) ---------
    if (bid < NKS * (POOL / 64)) {           // 16 * 16 = 256
        int ct = bid % (POOL / 64), kt = bid / (POOL / 64);
        gemm64<12, false>(g_xproj, prompt, g_spart + (size_t)kt * BATCH * POOL, POOL,
                          kt * 48, ct * 64, s_pool);
    }
    grid_sync();

    // -------- B4: reduce sim + scale + warp-register top-8 (64 CTAs) --------
    if (bid < BATCH) {
        int b = bid;
        float invx = rsqrtf(fmaxf(g_ssqp[b * 3 + 0] + g_ssqp[b * 3 + 1]
                                  + g_ssqp[b * 3 + 2], 1e-12f));
        float* sv = s_pool;                  // [1024]
#pragma unroll
        for (int j = 0; j < 4; j++) {
            int p = tid + 256 * j;
            float s = 0.f;
#pragma unroll
            for (int sp = 0; sp < NKS; sp++)
                s += g_spart[(size_t)sp * BATCH * POOL + (size_t)b * POOL + p];
            s *= g_invp[p] * invx;
            sv[p] = s;
            g_sim[b * POOL + p] = s;
        }
        __syncthreads();
        if (tid < 32) {
            float v[32];
#pragma unroll
            for (int j = 0; j < 32; j++) v[j] = sv[lane + 32 * j];
            int picks[TOPK];
            warp_top8_f(v, lane, picks);
            if (lane < TOPK) g_rowidx[b * TOPK + lane] = picks[lane];
        }
    }
    grid_sync();

    // -------- B5: vote (bincount + warp top-8 on counts) + reduce_sim -------
    if (bid == 0) {
        int*   cnt     = (int*)s_pool;       // [1024]
        float* rf      = s_pool + 1024;      // [256]
        int*   major_s = (int*)(s_pool + 1280);  // [8]
        for (int j = tid; j < POOL; j += 256) cnt[j] = 0;
        __syncthreads();
        for (int j = tid; j < BATCH * TOPK; j += 256) atomicAdd(&cnt[g_rowidx[j]], 1);
        __syncthreads();
        if (tid < 32) {
            float v[32];
#pragma unroll
            for (int j = 0; j < 32; j++) v[j] = (float)cnt[lane + 32 * j];  // counts <= 512: exact in fp32
            int picks[TOPK];
            warp_top8_f(v, lane, picks);
            if (lane < TOPK) { major_s[lane] = picks[lane]; g_major[lane] = picks[lane]; }
        }
        __syncthreads();
        float s = 0.f;
        for (int j = tid; j < BATCH * TOPK; j += 256) {
            int b = j >> 3, k = j & 7;
            s += g_sim[b * POOL + major_s[k]];
        }
        rf[tid] = s; __syncthreads();
        for (int st = 128; st > 0; st >>= 1) {
            if (tid < st) rf[tid] += rf[tid + st];
            __syncthreads();
        }
        if (tid == 0) out[0] = rf[0] / (float)BATCH;
    }
    grid_sync();

    // -------- B6: gather batched_prompt (scalar stores: out+1 alignment) ----
    for (int row = bid; row < BATCH * TOPK; row += G) {
        int k = row & 7;
        int pid = g_major[k];
        const float* src = prompt + (size_t)pid * DIM;
        float* dst = out + 1 + (size_t)row * DIM;
        if (tid < 192) {
            float4 v = ((const float4*)src)[tid];
            dst[tid * 4 + 0] = v.x;
            dst[tid * 4 + 1] = v.y;
            dst[tid * 4 + 2] = v.z;
            dst[tid * 4 + 3] = v.w;
        }
    }
}

extern "C" void kernel_launch(void* const* d_in, const int* in_sizes, int n_in,
                              void* d_out, int out_size) {
    const float* x      = (const float*)d_in[0];   // [64, 2048, 768]
    const float* prompt = (const float*)d_in[1];   // [1024, 768]
    const float* W      = (const float*)d_in[2];   // [768, 768]
    float* out = (float*)d_out;                    // [1 + 64*8*768]
    k_stream<<<SPLITS * BATCH + NORMC, 192>>>(x, prompt);
    k_tail  <<<G, 256>>>(prompt, W, out);
}

// round 13
// speedup vs baseline: 1.1615x; 1.0485x over previous
#include <cuda_runtime.h>
#include <float.h>

#define BATCH 64
#define TOK   2048
#define DIM   768
#define POOL  1024
#define TOPK  8
#define SPLITS 32
#define TOKS  64               // tokens per stream CTA
#define D4    192              // float4 per row
#define NKP   24               // proj split-K (KC=32): 24*12 = 288 jobs
#define NKS   16               // sim  split-K (KC=48): 16*16 = 256 jobs
#define G     296              // persistent tail grid: 2 CTAs/SM
#define NORMC 171              // prompt-norm CTAs in stream kernel
#define ZEROC 38               // accumulator-zeroing CTAs in stream kernel

// ---- scratch (static device arrays; no cudaMalloc anywhere) ----
__device__ unsigned g_xmax_enc[BATCH * DIM];   // zero-init < all encoded floats
__device__ float g_invp[POOL];
__device__ float g_xproj[BATCH * DIM];         // atomic-accumulated (zeroed by k_stream)
__device__ float g_sim[BATCH * POOL];          // atomic-accumulated (zeroed by k_stream)
__device__ int   g_rowidx[BATCH * TOPK];
__device__ unsigned g_count = 0;   // barrier state: self-resetting across replays
__device__ unsigned g_gen   = 0;

__device__ __forceinline__ float4 fmax4(float4 a, float4 b) {
    return make_float4(fmaxf(a.x, b.x), fmaxf(a.y, b.y),
                       fmaxf(a.z, b.z), fmaxf(a.w, b.w));
}
// order-preserving float <-> uint32 (monotone): max over keys == max over floats
__device__ __forceinline__ unsigned fenc(float f) {
    unsigned u = __float_as_uint(f);
    return (u & 0x80000000u) ? ~u : (u | 0x80000000u);
}
__device__ __forceinline__ float fdec(unsigned k) {
    unsigned u = (k & 0x80000000u) ? (k ^ 0x80000000u) : ~k;
    return __uint_as_float(u);
}

// ============ kernel A: stream max + prompt norms + accumulator zeroing ======
__global__ void __launch_bounds__(192)
k_stream(const float* __restrict__ x, const float* __restrict__ prompt) {
    int bid = blockIdx.x, tid = threadIdx.x;
    if (bid < SPLITS * BATCH) {
        int s = bid & (SPLITS - 1), b = bid >> 5;
        const float4* xp = (const float4*)x + ((size_t)b * TOK + (size_t)s * TOKS) * D4 + tid;
        float4 m0 = __ldcs(xp + 0 * D4), m1 = __ldcs(xp + 1 * D4);
        float4 m2 = __ldcs(xp + 2 * D4), m3 = __ldcs(xp + 3 * D4);
        float4 m4 = __ldcs(xp + 4 * D4), m5 = __ldcs(xp + 5 * D4);
        float4 m6 = __ldcs(xp + 6 * D4), m7 = __ldcs(xp + 7 * D4);
#pragma unroll 7
        for (int t = 8; t < TOKS; t += 8) {
            const float4* p = xp + (size_t)t * D4;
            m0 = fmax4(m0, __ldcs(p + 0 * D4));
            m1 = fmax4(m1, __ldcs(p + 1 * D4));
            m2 = fmax4(m2, __ldcs(p + 2 * D4));
            m3 = fmax4(m3, __ldcs(p + 3 * D4));
            m4 = fmax4(m4, __ldcs(p + 4 * D4));
            m5 = fmax4(m5, __ldcs(p + 5 * D4));
            m6 = fmax4(m6, __ldcs(p + 6 * D4));
            m7 = fmax4(m7, __ldcs(p + 7 * D4));
        }
        float4 r = fmax4(fmax4(fmax4(m0, m1), fmax4(m2, m3)),
                         fmax4(fmax4(m4, m5), fmax4(m6, m7)));
        unsigned* dst = g_xmax_enc + (size_t)b * DIM + tid * 4;
        atomicMax(dst + 0, fenc(r.x));
        atomicMax(dst + 1, fenc(r.y));
        atomicMax(dst + 2, fenc(r.z));
        atomicMax(dst + 3, fenc(r.w));
    } else if (bid < SPLITS * BATCH + NORMC) {
        int lane = tid & 31, w = tid >> 5;
        int p = (bid - SPLITS * BATCH) * 6 + w;
        if (p < POOL) {
            const float4* row = (const float4*)(prompt + (size_t)p * DIM);
            float s = 0.f;
#pragma unroll
            for (int j = lane; j < D4; j += 32) {
                float4 v = row[j];
                s += v.x * v.x + v.y * v.y + v.z * v.z + v.w * v.w;
            }
#pragma unroll
            for (int o = 16; o > 0; o >>= 1) s += __shfl_xor_sync(0xffffffffu, s, o);
            if (lane == 0) g_invp[p] = rsqrtf(fmaxf(s, 1e-12f));
        }
    } else {
        // zero the atomic accumulators for this replay
        int zc = bid - SPLITS * BATCH - NORMC;
        float4 z = make_float4(0.f, 0.f, 0.f, 0.f);
        for (int i = zc * 192 + tid; i < (BATCH * DIM) / 4; i += ZEROC * 192)
            ((float4*)g_xproj)[i] = z;
        for (int i = zc * 192 + tid; i < (BATCH * POOL) / 4; i += ZEROC * 192)
            ((float4*)g_sim)[i] = z;
    }
}

// ==================== kernel B: persistent tail ==============================
__device__ __forceinline__ void grid_sync() {
    __syncthreads();
    if (threadIdx.x == 0) {
        __threadfence();
        volatile unsigned* genp = &g_gen;
        unsigned gen = *genp;
        if (atomicAdd(&g_count, 1u) == G - 1) {
            *(volatile unsigned*)&g_count = 0;
            __threadfence();
            *genp = gen + 1;
        } else {
            while (*genp == gen) __nanosleep(32);
        }
        __threadfence();
    }
    __syncthreads();
}

// 64x64-tile split-K GEMM chunk, conflict-free smem, atomicAdd accumulation.
// K4 = float4 K-steps. DEC: A holds encoded-max keys (decode on load).
template <int K4, bool DEC>
__device__ __forceinline__ void gemm64_atom(const void* __restrict__ Araw,
                                            const float* __restrict__ B,
                                            float* __restrict__ dst, int cstride,
                                            int kc0, int c0, float* pool) {
    constexpr int SW = 4 * K4 + 4;           // SW % 4 == 0 (alignment), (SW/4) odd
    static_assert(((SW / 4) & 1) == 1, "SW16 must be odd for conflict-free LDS");
    float (*xs)[SW] = (float(*)[SW])pool;
    float (*ws)[SW] = (float(*)[SW])(pool + 64 * SW);
    int tid = threadIdx.x;
#pragma unroll
    for (int it = 0; it < K4 / 4; it++) {
        int idx = tid + it * 256;            // 0 .. 64*K4-1
        int r = idx / K4, c4 = idx % K4;
        if (DEC) {
            uint4 e = *(const uint4*)((const unsigned*)Araw + (size_t)r * DIM + kc0 + c4 * 4);
            *(float4*)&xs[r][c4 * 4] = make_float4(fdec(e.x), fdec(e.y), fdec(e.z), fdec(e.w));
        } else {
            *(float4*)&xs[r][c4 * 4] = *(const float4*)((const float*)Araw + (size_t)r * DIM + kc0 + c4 * 4);
        }
        *(float4*)&ws[r][c4 * 4] = *(const float4*)(B + (size_t)(c0 + r) * DIM + kc0 + c4 * 4);
    }
    __syncthreads();
    int tx = tid & 15, ty = tid >> 4;        // 16x16 threads; strided 4x4 micro-tile
    float acc[4][4];
#pragma unroll
    for (int i = 0; i < 4; i++)
#pragma unroll
        for (int j = 0; j < 4; j++) acc[i][j] = 0.f;
    float4 a[4], b[4], an[4], bn[4];
#pragma unroll
    for (int i = 0; i < 4; i++) {
        a[i] = *(float4*)&xs[ty + 16 * i][0];
        b[i] = *(float4*)&ws[tx + 16 * i][0];
    }
#pragma unroll
    for (int k4 = 0; k4 < K4; k4++) {
        if (k4 + 1 < K4) {                   // prefetch next k-step (hides LDS lat)
#pragma unroll
            for (int i = 0; i < 4; i++) {
                an[i] = *(float4*)&xs[ty + 16 * i][(k4 + 1) * 4];
                bn[i] = *(float4*)&ws[tx + 16 * i][(k4 + 1) * 4];
            }
        }
#pragma unroll
        for (int i = 0; i < 4; i++)
#pragma unroll
            for (int j = 0; j < 4; j++) {
                acc[i][j] += a[i].x * b[j].x;
                acc[i][j] += a[i].y * b[j].y;
                acc[i][j] += a[i].z * b[j].z;
                acc[i][j] += a[i].w * b[j].w;
            }
#pragma unroll
        for (int i = 0; i < 4; i++) { a[i] = an[i]; b[i] = bn[i]; }
    }
    __syncthreads();
    // atomic accumulation (REDG.F32): row ty+16i, col c0+tx+16j, coalesced in tx
#pragma unroll
    for (int i = 0; i < 4; i++)
#pragma unroll
        for (int j = 0; j < 4; j++)
            atomicAdd(&dst[(size_t)(ty + 16 * i) * cstride + c0 + tx + 16 * j], acc[i][j]);
}

// warp-register iterative top-8 with JAX tie rule (lowest index wins).
__device__ __forceinline__ void warp_top8_f(float* v, int lane, int* picks) {
    for (int k = 0; k < TOPK; k++) {
        float bv = -FLT_MAX; int bj = 0;
#pragma unroll
        for (int j = 0; j < 32; j++)
            if (v[j] > bv) { bv = v[j]; bj = j; }     // ascending j: lowest idx on tie
        float rv = bv; int rgi = lane + 32 * bj;
#pragma unroll
        for (int o = 16; o > 0; o >>= 1) {
            float ov = __shfl_xor_sync(0xffffffffu, rv, o);
            int   oi = __shfl_xor_sync(0xffffffffu, rgi, o);
            if (ov > rv || (ov == rv && oi < rgi)) { rv = ov; rgi = oi; }
        }
        picks[k] = rgi;
        if (lane == (rgi & 31)) {
            int slot = rgi >> 5;
#pragma unroll
            for (int j = 0; j < 32; j++)
                if (j == slot) v[j] = -FLT_MAX;
        }
    }
}

__global__ void __launch_bounds__(256, 2)
k_tail(const float* __restrict__ prompt, const float* __restrict__ W,
       float* __restrict__ out) {
    __shared__ float s_pool[2 * 64 * 52];   // 26.6 KB, phase-unioned (max SW=52)
    int tid = threadIdx.x, bid = blockIdx.x;
    int lane = tid & 31;

    // -------- T1: proj GEMM, keys decoded inline, atomicAdd -> g_xproj ------
    if (bid < NKP * (DIM / 64)) {            // 288 jobs
        int ct = bid % (DIM / 64), kt = bid / (DIM / 64);
        gemm64_atom<8, true>(g_xmax_enc, W, g_xproj, DIM, kt * 32, ct * 64, s_pool);
    }
    grid_sync();

    // -------- T2: sim GEMM on accumulated xproj, atomicAdd -> g_sim ---------
    if (bid < NKS * (POOL / 64)) {           // 256 jobs
        int ct = bid % (POOL / 64), kt = bid / (POOL / 64);
        gemm64_atom<12, false>(g_xproj, prompt, g_sim, POOL, kt * 48, ct * 64, s_pool);
    }
    grid_sync();

    // -------- T3: per-row ssq (deterministic) + scale + top-8 (64 CTAs) -----
    if (bid < BATCH) {
        int b = bid;
        float* red = s_pool + POOL;          // [256]
        float ss = 0.f;
#pragma unroll
        for (int j = 0; j < 3; j++) {
            float v = g_xproj[b * DIM + tid + 256 * j];
            ss += v * v;
        }
        red[tid] = ss; __syncthreads();
        for (int st = 128; st > 0; st >>= 1) {
            if (tid < st) red[tid] += red[tid + st];
            __syncthreads();
        }
        float invx = rsqrtf(fmaxf(red[0], 1e-12f));
        float* sv = s_pool;                  // [1024]
#pragma unroll
        for (int j = 0; j < 4; j++) {
            int p = tid + 256 * j;
            float s = g_sim[b * POOL + p] * g_invp[p] * invx;
            sv[p] = s;
            g_sim[b * POOL + p] = s;         // scaled, read by T4 reduce_sim
        }
        __syncthreads();
        if (tid < 32) {
            float v[32];
#pragma unroll
            for (int j = 0; j < 32; j++) v[j] = sv[lane + 32 * j];
            int picks[TOPK];
            warp_top8_f(v, lane, picks);
            if (lane < TOPK) g_rowidx[b * TOPK + lane] = picks[lane];
        }
    }
    grid_sync();

    // -------- T4: redundant vote (every CTA) + gather + reduce_sim + resets -
    {
        int*   cnt     = (int*)s_pool;           // [1024]
        float* rf      = s_pool + 1024;          // [256]
        int*   major_s = (int*)(s_pool + 1280);  // [8]
        for (int j = tid; j < POOL; j += 256) cnt[j] = 0;
        __syncthreads();
        for (int j = tid; j < BATCH * TOPK; j += 256) atomicAdd(&cnt[g_rowidx[j]], 1);
        __syncthreads();
        if (tid < 32) {
            float v[32];
#pragma unroll
            for (int j = 0; j < 32; j++) v[j] = (float)cnt[lane + 32 * j];  // counts <= 512: exact
            int picks[TOPK];
            warp_top8_f(v, lane, picks);
            if (lane < TOPK) major_s[lane] = picks[lane];
        }
        __syncthreads();

        if (bid == 0) {                      // reduce_sim (CTA 0 only)
            float s = 0.f;
            for (int j = tid; j < BATCH * TOPK; j += 256) {
                int b = j >> 3, k = j & 7;
                s += g_sim[b * POOL + major_s[k]];
            }
            rf[tid] = s; __syncthreads();
            for (int st = 128; st > 0; st >>= 1) {
                if (tid < st) rf[tid] += rf[tid + st];
                __syncthreads();
            }
            if (tid == 0) out[0] = rf[0] / (float)BATCH;
        }

        // gather batched_prompt (scalar stores: out+1 is only 4B-aligned)
        for (int row = bid; row < BATCH * TOPK; row += G) {
            int k = row & 7;
            int pid = major_s[k];
            const float* src = prompt + (size_t)pid * DIM;
            float* dst = out + 1 + (size_t)row * DIM;
            if (tid < 192) {
                float4 v = ((const float4*)src)[tid];
                dst[tid * 4 + 0] = v.x;
                dst[tid * 4 + 1] = v.y;
                dst[tid * 4 + 2] = v.z;
                dst[tid * 4 + 3] = v.w;
            }
        }

        // reset encoded-max keys for the next graph replay
        int i = bid * 256 + tid;
        if (i < BATCH * DIM) g_xmax_enc[i] = 0u;
    }
}

extern "C" void kernel_launch(void* const* d_in, const int* in_sizes, int n_in,
                              void* d_out, int out_size) {
    const float* x      = (const float*)d_in[0];   // [64, 2048, 768]
    const float* prompt = (const float*)d_in[1];   // [1024, 768]
    const float* W      = (const float*)d_in[2];   // [768, 768]
    float* out = (float*)d_out;                    // [1 + 64*8*768]
    k_stream<<<SPLITS * BATCH + NORMC + ZEROC, 192>>>(x, prompt);
    k_tail  <<<G, 256>>>(prompt, W, out);
}

// round 14
// speedup vs baseline: 1.1677x; 1.0053x over previous
#include <cuda_runtime.h>
#include <float.h>

#define BATCH 64
#define TOK   2048
#define DIM   768
#define POOL  1024
#define TOPK  8
#define SPLITS 32
#define TOKS  64               // tokens per stream CTA
#define D4    192              // float4 per row
#define NKP   24               // proj split-K (KC=32): 24*12 = 288 jobs
#define NKS   24               // sim  split-K (KC=32): 24*16 = 384 jobs
#define G     444              // persistent tail grid: 3 CTAs/SM on 148 SMs
#define NORMC 171              // prompt-norm CTAs in stream kernel
#define ZEROC 38               // accumulator-zeroing CTAs in stream kernel

// ---- scratch (static device arrays; no cudaMalloc anywhere) ----
__device__ unsigned g_xmax_enc[BATCH * DIM];   // zero-init < all encoded floats
__device__ float g_invp[POOL];
__device__ float g_xproj[BATCH * DIM];         // atomic-accumulated (zeroed by k_stream)
__device__ float g_sim[BATCH * POOL];          // atomic-accumulated (zeroed by k_stream)
__device__ int   g_rowidx[BATCH * TOPK];
__device__ unsigned g_count = 0;   // barrier state: self-resetting across replays
__device__ unsigned g_gen   = 0;

__device__ __forceinline__ float4 fmax4(float4 a, float4 b) {
    return make_float4(fmaxf(a.x, b.x), fmaxf(a.y, b.y),
                       fmaxf(a.z, b.z), fmaxf(a.w, b.w));
}
// order-preserving float <-> uint32 (monotone): max over keys == max over floats
__device__ __forceinline__ unsigned fenc(float f) {
    unsigned u = __float_as_uint(f);
    return (u & 0x80000000u) ? ~u : (u | 0x80000000u);
}
__device__ __forceinline__ float fdec(unsigned k) {
    unsigned u = (k & 0x80000000u) ? (k ^ 0x80000000u) : ~k;
    return __uint_as_float(u);
}

// ============ kernel A: stream max + prompt norms + accumulator zeroing ======
__global__ void __launch_bounds__(192)
k_stream(const float* __restrict__ x, const float* __restrict__ prompt) {
    int bid = blockIdx.x, tid = threadIdx.x;
    if (bid < SPLITS * BATCH) {
        int s = bid & (SPLITS - 1), b = bid >> 5;
        const float4* xp = (const float4*)x + ((size_t)b * TOK + (size_t)s * TOKS) * D4 + tid;
        float4 m0 = __ldcs(xp + 0 * D4), m1 = __ldcs(xp + 1 * D4);
        float4 m2 = __ldcs(xp + 2 * D4), m3 = __ldcs(xp + 3 * D4);
        float4 m4 = __ldcs(xp + 4 * D4), m5 = __ldcs(xp + 5 * D4);
        float4 m6 = __ldcs(xp + 6 * D4), m7 = __ldcs(xp + 7 * D4);
#pragma unroll 7
        for (int t = 8; t < TOKS; t += 8) {
            const float4* p = xp + (size_t)t * D4;
            m0 = fmax4(m0, __ldcs(p + 0 * D4));
            m1 = fmax4(m1, __ldcs(p + 1 * D4));
            m2 = fmax4(m2, __ldcs(p + 2 * D4));
            m3 = fmax4(m3, __ldcs(p + 3 * D4));
            m4 = fmax4(m4, __ldcs(p + 4 * D4));
            m5 = fmax4(m5, __ldcs(p + 5 * D4));
            m6 = fmax4(m6, __ldcs(p + 6 * D4));
            m7 = fmax4(m7, __ldcs(p + 7 * D4));
        }
        float4 r = fmax4(fmax4(fmax4(m0, m1), fmax4(m2, m3)),
                         fmax4(fmax4(m4, m5), fmax4(m6, m7)));
        unsigned* dst = g_xmax_enc + (size_t)b * DIM + tid * 4;
        atomicMax(dst + 0, fenc(r.x));
        atomicMax(dst + 1, fenc(r.y));
        atomicMax(dst + 2, fenc(r.z));
        atomicMax(dst + 3, fenc(r.w));
    } else if (bid < SPLITS * BATCH + NORMC) {
        int lane = tid & 31, w = tid >> 5;
        int p = (bid - SPLITS * BATCH) * 6 + w;
        if (p < POOL) {
            const float4* row = (const float4*)(prompt + (size_t)p * DIM);
            float s = 0.f;
#pragma unroll
            for (int j = lane; j < D4; j += 32) {
                float4 v = row[j];
                s += v.x * v.x + v.y * v.y + v.z * v.z + v.w * v.w;
            }
#pragma unroll
            for (int o = 16; o > 0; o >>= 1) s += __shfl_xor_sync(0xffffffffu, s, o);
            if (lane == 0) g_invp[p] = rsqrtf(fmaxf(s, 1e-12f));
        }
    } else {
        // zero the atomic accumulators for this replay
        int zc = bid - SPLITS * BATCH - NORMC;
        float4 z = make_float4(0.f, 0.f, 0.f, 0.f);
        for (int i = zc * 192 + tid; i < (BATCH * DIM) / 4; i += ZEROC * 192)
            ((float4*)g_xproj)[i] = z;
        for (int i = zc * 192 + tid; i < (BATCH * POOL) / 4; i += ZEROC * 192)
            ((float4*)g_sim)[i] = z;
    }
}

// ==================== kernel B: persistent tail ==============================
__device__ __forceinline__ void grid_sync() {
    __syncthreads();
    if (threadIdx.x == 0) {
        __threadfence();
        volatile unsigned* genp = &g_gen;
        unsigned gen = *genp;
        if (atomicAdd(&g_count, 1u) == G - 1) {
            *(volatile unsigned*)&g_count = 0;
            __threadfence();
            *genp = gen + 1;
        } else {
            while (*genp == gen) __nanosleep(32);
        }
        __threadfence();
    }
    __syncthreads();
}

// 64x64-tile split-K GEMM chunk, conflict-free smem, atomicAdd accumulation.
// K4 = float4 K-steps. DEC: A holds encoded-max keys (decode on load).
template <int K4, bool DEC>
__device__ __forceinline__ void gemm64_atom(const void* __restrict__ Araw,
                                            const float* __restrict__ B,
                                            float* __restrict__ dst, int cstride,
                                            int kc0, int c0, float* pool) {
    constexpr int SW = 4 * K4 + 4;           // SW % 4 == 0 (alignment), (SW/4) odd
    static_assert(((SW / 4) & 1) == 1, "SW16 must be odd for conflict-free LDS");
    float (*xs)[SW] = (float(*)[SW])pool;
    float (*ws)[SW] = (float(*)[SW])(pool + 64 * SW);
    int tid = threadIdx.x;
#pragma unroll
    for (int it = 0; it < K4 / 4; it++) {
        int idx = tid + it * 256;            // 0 .. 64*K4-1
        int r = idx / K4, c4 = idx % K4;
        if (DEC) {
            uint4 e = *(const uint4*)((const unsigned*)Araw + (size_t)r * DIM + kc0 + c4 * 4);
            *(float4*)&xs[r][c4 * 4] = make_float4(fdec(e.x), fdec(e.y), fdec(e.z), fdec(e.w));
        } else {
            *(float4*)&xs[r][c4 * 4] = *(const float4*)((const float*)Araw + (size_t)r * DIM + kc0 + c4 * 4);
        }
        *(float4*)&ws[r][c4 * 4] = *(const float4*)(B + (size_t)(c0 + r) * DIM + kc0 + c4 * 4);
    }
    __syncthreads();
    int tx = tid & 15, ty = tid >> 4;        // 16x16 threads; strided 4x4 micro-tile
    float acc[4][4];
#pragma unroll
    for (int i = 0; i < 4; i++)
#pragma unroll
        for (int j = 0; j < 4; j++) acc[i][j] = 0.f;
    float4 a[4], b[4], an[4], bn[4];
#pragma unroll
    for (int i = 0; i < 4; i++) {
        a[i] = *(float4*)&xs[ty + 16 * i][0];
        b[i] = *(float4*)&ws[tx + 16 * i][0];
    }
#pragma unroll
    for (int k4 = 0; k4 < K4; k4++) {
        if (k4 + 1 < K4) {                   // prefetch next k-step (hides LDS lat)
#pragma unroll
            for (int i = 0; i < 4; i++) {
                an[i] = *(float4*)&xs[ty + 16 * i][(k4 + 1) * 4];
                bn[i] = *(float4*)&ws[tx + 16 * i][(k4 + 1) * 4];
            }
        }
#pragma unroll
        for (int i = 0; i < 4; i++)
#pragma unroll
            for (int j = 0; j < 4; j++) {
                acc[i][j] += a[i].x * b[j].x;
                acc[i][j] += a[i].y * b[j].y;
                acc[i][j] += a[i].z * b[j].z;
                acc[i][j] += a[i].w * b[j].w;
            }
#pragma unroll
        for (int i = 0; i < 4; i++) { a[i] = an[i]; b[i] = bn[i]; }
    }
    __syncthreads();
    // atomic accumulation (REDG.F32): row ty+16i, col c0+tx+16j, coalesced in tx
#pragma unroll
    for (int i = 0; i < 4; i++)
#pragma unroll
        for (int j = 0; j < 4; j++)
            atomicAdd(&dst[(size_t)(ty + 16 * i) * cstride + c0 + tx + 16 * j], acc[i][j]);
}

// warp-register iterative top-8 with JAX tie rule (lowest index wins).
__device__ __forceinline__ void warp_top8_f(float* v, int lane, int* picks) {
    for (int k = 0; k < TOPK; k++) {
        float bv = -FLT_MAX; int bj = 0;
#pragma unroll
        for (int j = 0; j < 32; j++)
            if (v[j] > bv) { bv = v[j]; bj = j; }     // ascending j: lowest idx on tie
        float rv = bv; int rgi = lane + 32 * bj;
#pragma unroll
        for (int o = 16; o > 0; o >>= 1) {
            float ov = __shfl_xor_sync(0xffffffffu, rv, o);
            int   oi = __shfl_xor_sync(0xffffffffu, rgi, o);
            if (ov > rv || (ov == rv && oi < rgi)) { rv = ov; rgi = oi; }
        }
        picks[k] = rgi;
        if (lane == (rgi & 31)) {
            int slot = rgi >> 5;
#pragma unroll
            for (int j = 0; j < 32; j++)
                if (j == slot) v[j] = -FLT_MAX;
        }
    }
}

__global__ void __launch_bounds__(256, 3)
k_tail(const float* __restrict__ prompt, const float* __restrict__ W,
       float* __restrict__ out) {
    __shared__ float s_pool[2 * 64 * 36];   // 18.4 KB -> 3 CTAs/SM (max SW=36)
    int tid = threadIdx.x, bid = blockIdx.x;
    int lane = tid & 31;

    // -------- T1: proj GEMM, keys decoded inline, atomicAdd -> g_xproj ------
    if (bid < NKP * (DIM / 64)) {            // 288 jobs
        int ct = bid % (DIM / 64), kt = bid / (DIM / 64);
        gemm64_atom<8, true>(g_xmax_enc, W, g_xproj, DIM, kt * 32, ct * 64, s_pool);
    }
    grid_sync();

    // -------- T2: sim GEMM on accumulated xproj, atomicAdd -> g_sim ---------
    if (bid < NKS * (POOL / 64)) {           // 384 jobs
        int ct = bid % (POOL / 64), kt = bid / (POOL / 64);
        gemm64_atom<8, false>(g_xproj, prompt, g_sim, POOL, kt * 32, ct * 64, s_pool);
    }
    grid_sync();

    // -------- T3: per-row ssq (deterministic) + scale + top-8 (64 CTAs) -----
    if (bid < BATCH) {
        int b = bid;
        float* red = s_pool + POOL;          // [256]
        float ss = 0.f;
#pragma unroll
        for (int j = 0; j < 3; j++) {
            float v = g_xproj[b * DIM + tid + 256 * j];
            ss += v * v;
        }
        red[tid] = ss; __syncthreads();
        for (int st = 128; st > 0; st >>= 1) {
            if (tid < st) red[tid] += red[tid + st];
            __syncthreads();
        }
        float invx = rsqrtf(fmaxf(red[0], 1e-12f));
        float* sv = s_pool;                  // [1024]
#pragma unroll
        for (int j = 0; j < 4; j++) {
            int p = tid + 256 * j;
            float s = g_sim[b * POOL + p] * g_invp[p] * invx;
            sv[p] = s;
            g_sim[b * POOL + p] = s;         // scaled, read by T4 reduce_sim
        }
        __syncthreads();
        if (tid < 32) {
            float v[32];
#pragma unroll
            for (int j = 0; j < 32; j++) v[j] = sv[lane + 32 * j];
            int picks[TOPK];
            warp_top8_f(v, lane, picks);
            if (lane < TOPK) g_rowidx[b * TOPK + lane] = picks[lane];
        }
    }
    grid_sync();

    // -------- T4: redundant vote (every CTA) + gather + reduce_sim + resets -
    {
        int*   cnt     = (int*)s_pool;           // [1024]
        float* rf      = s_pool + 1024;          // [256]
        int*   major_s = (int*)(s_pool + 1280);  // [8]
        for (int j = tid; j < POOL; j += 256) cnt[j] = 0;
        __syncthreads();
        for (int j = tid; j < BATCH * TOPK; j += 256) atomicAdd(&cnt[g_rowidx[j]], 1);
        __syncthreads();
        if (tid < 32) {
            float v[32];
#pragma unroll
            for (int j = 0; j < 32; j++) v[j] = (float)cnt[lane + 32 * j];  // counts <= 512: exact
            int picks[TOPK];
            warp_top8_f(v, lane, picks);
            if (lane < TOPK) major_s[lane] = picks[lane];
        }
        __syncthreads();

        if (bid == 0) {                      // reduce_sim (CTA 0 only)
            float s = 0.f;
            for (int j = tid; j < BATCH * TOPK; j += 256) {
                int b = j >> 3, k = j & 7;
                s += g_sim[b * POOL + major_s[k]];
            }
            rf[tid] = s; __syncthreads();
            for (int st = 128; st > 0; st >>= 1) {
                if (tid < st) rf[tid] += rf[tid + st];
                __syncthreads();
            }
            if (tid == 0) out[0] = rf[0] / (float)BATCH;
        }

        // gather batched_prompt (scalar stores: out+1 is only 4B-aligned)
        for (int row = bid; row < BATCH * TOPK; row += G) {
            int k = row & 7;
            int pid = major_s[k];
            const float* src = prompt + (size_t)pid * DIM;
            float* dst = out + 1 + (size_t)row * DIM;
            if (tid < 192) {
                float4 v = ((const float4*)src)[tid];
                dst[tid * 4 + 0] = v.x;
                dst[tid * 4 + 1] = v.y;
                dst[tid * 4 + 2] = v.z;
                dst[tid * 4 + 3] = v.w;
            }
        }

        // reset encoded-max keys for the next graph replay
        int i = bid * 256 + tid;
        if (i < BATCH * DIM) g_xmax_enc[i] = 0u;
    }
}

extern "C" void kernel_launch(void* const* d_in, const int* in_sizes, int n_in,
                              void* d_out, int out_size) {
    const float* x      = (const float*)d_in[0];   // [64, 2048, 768]
    const float* prompt = (const float*)d_in[1];   // [1024, 768]
    const float* W      = (const float*)d_in[2];   // [768, 768]
    float* out = (float*)d_out;                    // [1 + 64*8*768]
    k_stream<<<SPLITS * BATCH + NORMC + ZEROC, 192>>>(x, prompt);
    k_tail  <<<G, 256>>>(prompt, W, out);
}